// round 1
// baseline (speedup 1.0000x reference)
#include <cuda_runtime.h>

#define CTXL 8192
#define QL   128
#define KVL  8320
#define HIDN 4096
#define NH   32
#define NKV  8
#define HD   128

// ---------------- scratch (static device allocations) ----------------
__device__ float g_q_raw[4 * QL * HIDN];                 // 8 MB
__device__ float g_Q[4 * NH * QL * HD];                  // 8 MB  [B,H,Q,D]
__device__ float g_k_raw[(size_t)4 * KVL * NKV * HD];    // 136 MB
__device__ float g_K[(size_t)4 * NKV * KVL * HD];        // 136 MB [B,KVH,T,D]
__device__ float g_v_raw[(size_t)4 * KVL * NKV * HD];    // 136 MB (used directly as V)
__device__ float g_attn[4 * QL * HIDN];                  // 8 MB  [B*Q, H*D]

// ---------------- SGEMM: C[M,N] = A[M,K] @ W[N,K]^T ----------------
// MODE 0: A is a plain [M,K] row-major matrix.
// MODE 1: rows of A are the concat of target_hidden[B,CTXL,K] and hidden[B,QL,K]
//         (A = hidden, A2 = target_hidden), M = 4*KVL.
template <int MODE>
__global__ void __launch_bounds__(256)
sgemm_kernel(const float* __restrict__ A, const float* __restrict__ A2,
             const float* __restrict__ W, float* __restrict__ C,
             int M, int N, int K)
{
    __shared__ float As[16][132];
    __shared__ float Bs[16][132];

    const int m0 = blockIdx.y * 128;
    const int n0 = blockIdx.x * 128;
    const int tid = threadIdx.x;
    const int ty = tid >> 4;
    const int tx = tid & 15;
    const int lrow = tid >> 1;          // 0..127
    const int lcol = (tid & 1) * 8;     // 0 or 8

    const float* aptr;
    {
        const int am = m0 + lrow;
        if (MODE == 0) {
            aptr = A + (size_t)am * K + lcol;
        } else {
            const int b = am / KVL;
            const int t = am - b * KVL;
            if (t < CTXL) aptr = A2 + ((size_t)b * CTXL + t) * K + lcol;
            else          aptr = A  + ((size_t)b * QL + (t - CTXL)) * K + lcol;
        }
    }
    const float* wptr = W + (size_t)(n0 + lrow) * K + lcol;

    float acc[8][8];
#pragma unroll
    for (int i = 0; i < 8; i++)
#pragma unroll
        for (int j = 0; j < 8; j++) acc[i][j] = 0.f;

    float4 pa0 = *(const float4*)(aptr);
    float4 pa1 = *(const float4*)(aptr + 4);
    float4 pb0 = *(const float4*)(wptr);
    float4 pb1 = *(const float4*)(wptr + 4);

    const int nk = K >> 4;
    for (int kt = 0; kt < nk; ++kt) {
        As[lcol + 0][lrow] = pa0.x; As[lcol + 1][lrow] = pa0.y;
        As[lcol + 2][lrow] = pa0.z; As[lcol + 3][lrow] = pa0.w;
        As[lcol + 4][lrow] = pa1.x; As[lcol + 5][lrow] = pa1.y;
        As[lcol + 6][lrow] = pa1.z; As[lcol + 7][lrow] = pa1.w;
        Bs[lcol + 0][lrow] = pb0.x; Bs[lcol + 1][lrow] = pb0.y;
        Bs[lcol + 2][lrow] = pb0.z; Bs[lcol + 3][lrow] = pb0.w;
        Bs[lcol + 4][lrow] = pb1.x; Bs[lcol + 5][lrow] = pb1.y;
        Bs[lcol + 6][lrow] = pb1.z; Bs[lcol + 7][lrow] = pb1.w;
        __syncthreads();

        if (kt + 1 < nk) {   // prefetch next k-slab into registers
            const float* ap = aptr + (size_t)(kt + 1) * 16;
            pa0 = *(const float4*)(ap);
            pa1 = *(const float4*)(ap + 4);
            const float* bp = wptr + (size_t)(kt + 1) * 16;
            pb0 = *(const float4*)(bp);
            pb1 = *(const float4*)(bp + 4);
        }

#pragma unroll
        for (int k = 0; k < 16; ++k) {
            float a[8], bb[8];
            *(float4*)&a[0]  = *(const float4*)&As[k][ty * 8];
            *(float4*)&a[4]  = *(const float4*)&As[k][ty * 8 + 4];
            *(float4*)&bb[0] = *(const float4*)&Bs[k][tx * 8];
            *(float4*)&bb[4] = *(const float4*)&Bs[k][tx * 8 + 4];
#pragma unroll
            for (int i = 0; i < 8; i++)
#pragma unroll
                for (int j = 0; j < 8; j++)
                    acc[i][j] += a[i] * bb[j];
        }
        __syncthreads();
    }

#pragma unroll
    for (int i = 0; i < 8; i++) {
        float* cp = C + (size_t)(m0 + ty * 8 + i) * N + n0 + tx * 8;
        *(float4*)cp       = make_float4(acc[i][0], acc[i][1], acc[i][2], acc[i][3]);
        *(float4*)(cp + 4) = make_float4(acc[i][4], acc[i][5], acc[i][6], acc[i][7]);
    }
}

// ---------------- fused RMSNorm + RoPE ----------------
// raw[(b*seq+t)*rawld + h*HD + d] -> out[((b*heads+h)*seq + t)*HD + d]
__global__ void norm_rope_kernel(const float* __restrict__ raw, float* __restrict__ out,
                                 const float* __restrict__ w,
                                 const float* __restrict__ cosb, const float* __restrict__ sinb,
                                 int heads, int seq, int rawld, int pos_off)
{
    const int bid = blockIdx.x;
    const int t = bid % seq;
    const int h = (bid / seq) % heads;
    const int b = bid / (seq * heads);
    const int d = threadIdx.x;

    const float* rp = raw + ((size_t)(b * seq + t)) * rawld + h * HD;
    float x = rp[d];
    float ss = x * x;
#pragma unroll
    for (int off = 16; off > 0; off >>= 1)
        ss += __shfl_xor_sync(0xffffffffu, ss, off);

    __shared__ float sred[4];
    __shared__ float xs[128];
    if ((d & 31) == 0) sred[d >> 5] = ss;
    __syncthreads();
    ss = sred[0] + sred[1] + sred[2] + sred[3];
    const float r = rsqrtf(ss * (1.0f / 128.0f) + 1e-6f);
    const float xn = x * r * w[d];
    xs[d] = xn;
    __syncthreads();
    const float rot = (d < 64) ? -xs[d + 64] : xs[d - 64];
    const size_t pidx = ((size_t)b * KVL + (size_t)(pos_off + t)) * HD + d;
    out[(((size_t)(b * heads + h)) * seq + t) * HD + d] = xn * cosb[pidx] + rot * sinb[pidx];
}

// ---------------- flash attention: one block per (b,h) ----------------
#define APAD 132
__global__ void __launch_bounds__(256)
attn_kernel(const float* __restrict__ Qm,   // [B,H,Q,D]
            const float* __restrict__ Km,   // [B,KVH,T,D]
            const float* __restrict__ Vr,   // raw v proj [(b*T+t)*1024 + kvh*128 + d]
            float* __restrict__ out)        // [B*Q, H*D]
{
    extern __shared__ float sm[];
    float* Qs = sm;                  // [128][APAD] layout (d, q)
    float* Ks = sm + 128 * APAD;     // (d, j) for QK^T, then P as (q, j)
    float* Vs = sm + 2 * 128 * APAD; // (j, d)

    const int b   = blockIdx.x >> 5;
    const int h   = blockIdx.x & 31;
    const int kvh = h >> 2;
    const int tid = threadIdx.x;
    const int ty = tid >> 4, tx = tid & 15;
    const int lrow = tid >> 1;
    const int lc0  = (tid & 1) * 64;

    const float scale = 0.08838834764831845f;  // 128^-0.5

    // load Q transposed (and pre-scale)
    const float* qg = Qm + ((size_t)(b * NH + h)) * QL * HD;
#pragma unroll
    for (int it = 0; it < 16; ++it) {
        const int col = lc0 + it * 4;
        float4 v = *(const float4*)(qg + lrow * HD + col);
        Qs[(col + 0) * APAD + lrow] = v.x * scale;
        Qs[(col + 1) * APAD + lrow] = v.y * scale;
        Qs[(col + 2) * APAD + lrow] = v.z * scale;
        Qs[(col + 3) * APAD + lrow] = v.w * scale;
    }

    float O[8][8];
    float mr[8], lr[8];
#pragma unroll
    for (int i = 0; i < 8; i++) {
        mr[i] = -1e30f; lr[i] = 0.f;
#pragma unroll
        for (int j = 0; j < 8; j++) O[i][j] = 0.f;
    }

    const float* kg = Km + ((size_t)(b * NKV + kvh)) * KVL * HD;
    const float* vg = Vr + (size_t)b * KVL * (NKV * HD) + kvh * HD;

    for (int c = 0; c < KVL / 128; ++c) {
        const int t0 = c * 128;
        __syncthreads();  // previous PV done (and Q load on first iter)

        // K chunk, transposed to (d, j)
#pragma unroll
        for (int it = 0; it < 16; ++it) {
            const int col = lc0 + it * 4;
            float4 v = *(const float4*)(kg + (size_t)(t0 + lrow) * HD + col);
            Ks[(col + 0) * APAD + lrow] = v.x;
            Ks[(col + 1) * APAD + lrow] = v.y;
            Ks[(col + 2) * APAD + lrow] = v.z;
            Ks[(col + 3) * APAD + lrow] = v.w;
        }
        // V chunk, row-major (j, d)
#pragma unroll
        for (int it = 0; it < 16; ++it) {
            const int idx = tid + it * 256;
            const int j = idx >> 5;
            const int c4 = (idx & 31) * 4;
            *(float4*)&Vs[j * APAD + c4] =
                *(const float4*)(vg + (size_t)(t0 + j) * (NKV * HD) + c4);
        }
        __syncthreads();

        // S = Q @ K^T  (8x8 fragment per thread)
        float S[8][8];
#pragma unroll
        for (int i = 0; i < 8; i++)
#pragma unroll
            for (int j = 0; j < 8; j++) S[i][j] = 0.f;

#pragma unroll 2
        for (int d = 0; d < 128; ++d) {
            float a[8], bb[8];
            *(float4*)&a[0]  = *(const float4*)&Qs[d * APAD + ty * 8];
            *(float4*)&a[4]  = *(const float4*)&Qs[d * APAD + ty * 8 + 4];
            *(float4*)&bb[0] = *(const float4*)&Ks[d * APAD + tx * 8];
            *(float4*)&bb[4] = *(const float4*)&Ks[d * APAD + tx * 8 + 4];
#pragma unroll
            for (int i = 0; i < 8; i++)
#pragma unroll
                for (int j = 0; j < 8; j++)
                    S[i][j] += a[i] * bb[j];
        }

        // online softmax (row stats redundantly tracked per 16-lane group)
#pragma unroll
        for (int i = 0; i < 8; ++i) {
            float mx = S[i][0];
#pragma unroll
            for (int j = 1; j < 8; j++) mx = fmaxf(mx, S[i][j]);
#pragma unroll
            for (int off = 8; off > 0; off >>= 1)
                mx = fmaxf(mx, __shfl_xor_sync(0xffffffffu, mx, off));
            const float mn = fmaxf(mr[i], mx);
            const float corr = __expf(mr[i] - mn);
            float rs = 0.f;
#pragma unroll
            for (int j = 0; j < 8; j++) {
                const float p = __expf(S[i][j] - mn);
                S[i][j] = p;
                rs += p;
            }
#pragma unroll
            for (int off = 8; off > 0; off >>= 1)
                rs += __shfl_xor_sync(0xffffffffu, rs, off);
            lr[i] = lr[i] * corr + rs;
            mr[i] = mn;
#pragma unroll
            for (int j = 0; j < 8; j++) O[i][j] *= corr;
        }

        __syncthreads();  // everyone done reading Ks
        // write P row-major (q, j) into the Ks buffer (float4, conflict-free)
#pragma unroll
        for (int i = 0; i < 8; i++) {
            *(float4*)&Ks[(ty * 8 + i) * APAD + tx * 8] =
                make_float4(S[i][0], S[i][1], S[i][2], S[i][3]);
            *(float4*)&Ks[(ty * 8 + i) * APAD + tx * 8 + 4] =
                make_float4(S[i][4], S[i][5], S[i][6], S[i][7]);
        }
        __syncthreads();

        // O += P @ V
#pragma unroll 4
        for (int j = 0; j < 128; ++j) {
            float bb[8];
            *(float4*)&bb[0] = *(const float4*)&Vs[j * APAD + tx * 8];
            *(float4*)&bb[4] = *(const float4*)&Vs[j * APAD + tx * 8 + 4];
#pragma unroll
            for (int i = 0; i < 8; i++) {
                const float p = Ks[(ty * 8 + i) * APAD + j];  // broadcast across tx
#pragma unroll
                for (int jj = 0; jj < 8; jj++) O[i][jj] += p * bb[jj];
            }
        }
    }

    // epilogue
#pragma unroll
    for (int i = 0; i < 8; i++) {
        const float inv = 1.0f / lr[i];
        const int q = ty * 8 + i;
        float* op = out + ((size_t)(b * QL + q)) * HIDN + h * HD + tx * 8;
        *(float4*)op       = make_float4(O[i][0] * inv, O[i][1] * inv, O[i][2] * inv, O[i][3] * inv);
        *(float4*)(op + 4) = make_float4(O[i][4] * inv, O[i][5] * inv, O[i][6] * inv, O[i][7] * inv);
    }
}

// ---------------- launcher ----------------
extern "C" void kernel_launch(void* const* d_in, const int* in_sizes, int n_in,
                              void* d_out, int out_size)
{
    const float* hidden = (const float*)d_in[0];
    const float* target = (const float*)d_in[1];
    const float* cosb   = (const float*)d_in[2];
    const float* sinb   = (const float*)d_in[3];
    const float* Wq     = (const float*)d_in[4];
    const float* Wk     = (const float*)d_in[5];
    const float* Wv     = (const float*)d_in[6];
    const float* Wo     = (const float*)d_in[7];
    const float* qw     = (const float*)d_in[8];
    const float* kw     = (const float*)d_in[9];
    float* out = (float*)d_out;

    float *q_raw, *Qp, *k_raw, *Kp, *v_raw, *attn;
    cudaGetSymbolAddress((void**)&q_raw, g_q_raw);
    cudaGetSymbolAddress((void**)&Qp,    g_Q);
    cudaGetSymbolAddress((void**)&k_raw, g_k_raw);
    cudaGetSymbolAddress((void**)&Kp,    g_K);
    cudaGetSymbolAddress((void**)&v_raw, g_v_raw);
    cudaGetSymbolAddress((void**)&attn,  g_attn);

    const int attn_smem = 3 * 128 * APAD * 4;
    cudaFuncSetAttribute(attn_kernel, cudaFuncAttributeMaxDynamicSharedMemorySize, attn_smem);

    // Q projection: [512,4096] = hidden @ Wq^T
    sgemm_kernel<0><<<dim3(HIDN / 128, (4 * QL) / 128), 256>>>(
        hidden, nullptr, Wq, q_raw, 4 * QL, HIDN, HIDN);

    // K / V projections over concat(target, hidden): [33280,1024]
    sgemm_kernel<1><<<dim3((NKV * HD) / 128, (4 * KVL) / 128), 256>>>(
        hidden, target, Wk, k_raw, 4 * KVL, NKV * HD, HIDN);
    sgemm_kernel<1><<<dim3((NKV * HD) / 128, (4 * KVL) / 128), 256>>>(
        hidden, target, Wv, v_raw, 4 * KVL, NKV * HD, HIDN);

    // RMSNorm + RoPE
    norm_rope_kernel<<<4 * NH * QL, 128>>>(q_raw, Qp, qw, cosb, sinb, NH, QL, HIDN, CTXL);
    norm_rope_kernel<<<4 * NKV * KVL, 128>>>(k_raw, Kp, kw, cosb, sinb, NKV, KVL, NKV * HD, 0);

    // attention
    attn_kernel<<<4 * NH, 256, attn_smem>>>(Qp, Kp, v_raw, attn);

    // output projection -> d_out
    sgemm_kernel<0><<<dim3(HIDN / 128, (4 * QL) / 128), 256>>>(
        attn, nullptr, Wo, out, 4 * QL, HIDN, HIDN);
}

// round 3
// speedup vs baseline: 1.8770x; 1.8770x over previous
#include <cuda_runtime.h>
#include <cuda_bf16.h>
#include <cstdint>

#define CTXL 8192
#define QL   128
#define KVL  8320
#define HIDN 4096
#define NH   32
#define NKV  8
#define HD   128

// ---------------- scratch (static device allocations) ----------------
__device__ float g_q_raw[4 * QL * HIDN];                 // 8 MB
__device__ float g_Q[4 * NH * QL * HD];                  // 8 MB  [B,H,Q,D]
__device__ float g_k_raw[(size_t)4 * KVL * NKV * HD];    // 136 MB
__device__ float g_K[(size_t)4 * NKV * KVL * HD];        // 136 MB [B,KVH,T,D]
__device__ float g_v_raw[(size_t)4 * KVL * NKV * HD];    // 136 MB (used directly as V)
__device__ float g_attn[4 * QL * HIDN];                  // 8 MB  [B*Q, H*D]

// ================= helpers =================
__device__ __forceinline__ uint32_t smem_u32(const void* p) {
    uint32_t a;
    asm("{ .reg .u64 t; cvta.to.shared.u64 t, %1; cvt.u32.u64 %0, t; }" : "=r"(a) : "l"(p));
    return a;
}
__device__ __forceinline__ void ldsm_x4(uint32_t addr, uint32_t* r) {
    asm volatile("ldmatrix.sync.aligned.m8n8.x4.shared.b16 {%0,%1,%2,%3}, [%4];"
                 : "=r"(r[0]), "=r"(r[1]), "=r"(r[2]), "=r"(r[3]) : "r"(addr));
}
__device__ __forceinline__ void mma16816(float* c, const uint32_t* a, const uint32_t* b) {
    asm volatile(
        "mma.sync.aligned.m16n8k16.row.col.f32.bf16.bf16.f32 "
        "{%0,%1,%2,%3}, {%4,%5,%6,%7}, {%8,%9}, {%0,%1,%2,%3};"
        : "+f"(c[0]), "+f"(c[1]), "+f"(c[2]), "+f"(c[3])
        : "r"(a[0]), "r"(a[1]), "r"(a[2]), "r"(a[3]), "r"(b[0]), "r"(b[1]));
}

// split fp32 -> (hi, lo) bf16, 8 elems packed into two uint4
__device__ __forceinline__ void split8(float4 a, float4 b, uint4& hi, uint4& lo) {
    float x[8] = {a.x, a.y, a.z, a.w, b.x, b.y, b.z, b.w};
    unsigned h[8], l[8];
#pragma unroll
    for (int i = 0; i < 8; i++) {
        __nv_bfloat16 hb = __float2bfloat16(x[i]);
        float r = x[i] - __bfloat162float(hb);
        __nv_bfloat16 lb = __float2bfloat16(r);
        h[i] = (unsigned)__bfloat16_as_ushort(hb);
        l[i] = (unsigned)__bfloat16_as_ushort(lb);
    }
    hi = make_uint4(h[0] | (h[1] << 16), h[2] | (h[3] << 16),
                    h[4] | (h[5] << 16), h[6] | (h[7] << 16));
    lo = make_uint4(l[0] | (l[1] << 16), l[2] | (l[3] << 16),
                    l[4] | (l[5] << 16), l[6] | (l[7] << 16));
}

// ============ HMMA GEMM: C[M,N] fp32 = A[M,K] @ W[N,K]^T  (bf16 3-term split) ============
// MODE 0: A plain row-major [M,K].
// MODE 1: A rows = concat(target_hidden[B,CTXL,K], hidden[B,QL,K]) per batch (M=4*KVL).
#define KC 32
#define ROWB 80                    // bytes per smem row (32 bf16 + 8 pad)
#define TILEB (128 * ROWB)         // 10240
#define STAGEB (4 * TILEB)         // Ah Al Bh Bl = 40960
#define GEMM_SMEM (2 * STAGEB)     // 81920

template <int MODE>
__global__ void __launch_bounds__(256)
gemm_mma(const float* __restrict__ A, const float* __restrict__ A2,
         const float* __restrict__ W, float* __restrict__ C,
         int M, int N, int K)
{
    extern __shared__ char sm[];
    const uint32_t smb = smem_u32(sm);
    const int tid = threadIdx.x;
    const int l = tid & 31;
    const int w = tid >> 5;

    const int m0 = blockIdx.y * 128;
    const int n0 = blockIdx.x * 128;

    // ---- global load mapping: thread -> (row = tid>>1, 16-col segment = tid&1)
    const int lrow = tid >> 1;
    const int lseg = tid & 1;
    const float* aptr;
    {
        const int am = m0 + lrow;
        if (MODE == 0) {
            aptr = A + (size_t)am * K + lseg * 16;
        } else {
            const int b = am / KVL;
            const int t = am - b * KVL;
            aptr = (t < CTXL)
                ? A2 + ((size_t)b * CTXL + t) * K + lseg * 16
                : A  + ((size_t)b * QL + (t - CTXL)) * K + lseg * 16;
        }
    }
    const float* bptr = W + (size_t)(n0 + lrow) * K + lseg * 16;
    const uint32_t soff = (uint32_t)lrow * ROWB + (uint32_t)lseg * 32;

    // ---- ldmatrix lane addressing
    const int wm = (w & 3) * 32;   // warp M offset (4 warps along M)
    const int wn = (w >> 2) * 64;  // warp N offset (2 warps along N)
    const uint32_t a_off = (uint32_t)(wm + (l & 15)) * ROWB + (uint32_t)(l >> 4) * 16;
    const uint32_t b_off = (uint32_t)(wn + (l & 7) + ((l >> 4) & 1) * 8) * ROWB
                         + (uint32_t)((l >> 3) & 1) * 16;

    float acc[2][8][4];
#pragma unroll
    for (int i = 0; i < 2; i++)
#pragma unroll
        for (int j = 0; j < 8; j++)
#pragma unroll
            for (int k = 0; k < 4; k++) acc[i][j][k] = 0.f;

    const int nk = K / KC;
    float4 pa[4], pb[4];
    {
        pa[0] = *(const float4*)(aptr);      pa[1] = *(const float4*)(aptr + 4);
        pa[2] = *(const float4*)(aptr + 8);  pa[3] = *(const float4*)(aptr + 12);
        pb[0] = *(const float4*)(bptr);      pb[1] = *(const float4*)(bptr + 4);
        pb[2] = *(const float4*)(bptr + 8);  pb[3] = *(const float4*)(bptr + 12);
    }

    for (int c = 0; c < nk; ++c) {
        char* stp = sm + (c & 1) * STAGEB;
        // store prefetched chunk (split to hi/lo on the fly)
        {
            uint4 h0, l0, h1, l1;
            split8(pa[0], pa[1], h0, l0);
            split8(pa[2], pa[3], h1, l1);
            *(uint4*)(stp + soff)              = h0;
            *(uint4*)(stp + soff + 16)         = h1;
            *(uint4*)(stp + TILEB + soff)      = l0;
            *(uint4*)(stp + TILEB + soff + 16) = l1;
            split8(pb[0], pb[1], h0, l0);
            split8(pb[2], pb[3], h1, l1);
            *(uint4*)(stp + 2 * TILEB + soff)              = h0;
            *(uint4*)(stp + 2 * TILEB + soff + 16)         = h1;
            *(uint4*)(stp + 3 * TILEB + soff)      = l0;
            *(uint4*)(stp + 3 * TILEB + soff + 16) = l1;
        }
        __syncthreads();

        if (c + 1 < nk) {   // prefetch next chunk (latency hidden by MMA below)
            const float* ap = aptr + (size_t)(c + 1) * KC;
            pa[0] = *(const float4*)(ap);      pa[1] = *(const float4*)(ap + 4);
            pa[2] = *(const float4*)(ap + 8);  pa[3] = *(const float4*)(ap + 12);
            const float* bp = bptr + (size_t)(c + 1) * KC;
            pb[0] = *(const float4*)(bp);      pb[1] = *(const float4*)(bp + 4);
            pb[2] = *(const float4*)(bp + 8);  pb[3] = *(const float4*)(bp + 12);
        }

        const uint32_t base = smb + (uint32_t)(c & 1) * STAGEB;
#pragma unroll
        for (int ks = 0; ks < 2; ++ks) {
            uint32_t ah[2][4], al[2][4];
            const uint32_t ka = base + a_off + ks * 32;
            ldsm_x4(ka, ah[0]);
            ldsm_x4(ka + 16 * ROWB, ah[1]);
            ldsm_x4(ka + TILEB, al[0]);
            ldsm_x4(ka + TILEB + 16 * ROWB, al[1]);

            const uint32_t kb = base + 2 * TILEB + b_off + ks * 32;
#pragma unroll
            for (int ng = 0; ng < 4; ++ng) {
                uint32_t bh[4], bl[4];
                ldsm_x4(kb + ng * 16 * ROWB, bh);
                ldsm_x4(kb + TILEB + ng * 16 * ROWB, bl);
#pragma unroll
                for (int mf = 0; mf < 2; ++mf) {
                    mma16816(acc[mf][ng * 2 + 0], ah[mf], bh + 0);
                    mma16816(acc[mf][ng * 2 + 1], ah[mf], bh + 2);
                    mma16816(acc[mf][ng * 2 + 0], ah[mf], bl + 0);
                    mma16816(acc[mf][ng * 2 + 1], ah[mf], bl + 2);
                    mma16816(acc[mf][ng * 2 + 0], al[mf], bh + 0);
                    mma16816(acc[mf][ng * 2 + 1], al[mf], bh + 2);
                }
            }
        }
        __syncthreads();
    }

    // ---- epilogue: fragment layout -> C
#pragma unroll
    for (int mf = 0; mf < 2; ++mf) {
        const int r0 = m0 + wm + mf * 16 + (l >> 2);
#pragma unroll
        for (int nf = 0; nf < 8; ++nf) {
            const int col = n0 + wn + nf * 8 + (l & 3) * 2;
            float* p = C + (size_t)r0 * N + col;
            *(float2*)p             = make_float2(acc[mf][nf][0], acc[mf][nf][1]);
            *(float2*)(p + 8 * (size_t)N) = make_float2(acc[mf][nf][2], acc[mf][nf][3]);
        }
    }
}

// ---------------- fused RMSNorm + RoPE ----------------
__global__ void norm_rope_kernel(const float* __restrict__ raw, float* __restrict__ out,
                                 const float* __restrict__ w,
                                 const float* __restrict__ cosb, const float* __restrict__ sinb,
                                 int heads, int seq, int rawld, int pos_off)
{
    const int bid = blockIdx.x;
    const int t = bid % seq;
    const int h = (bid / seq) % heads;
    const int b = bid / (seq * heads);
    const int d = threadIdx.x;

    const float* rp = raw + ((size_t)(b * seq + t)) * rawld + h * HD;
    float x = rp[d];
    float ss = x * x;
#pragma unroll
    for (int off = 16; off > 0; off >>= 1)
        ss += __shfl_xor_sync(0xffffffffu, ss, off);

    __shared__ float sred[4];
    __shared__ float xs[128];
    if ((d & 31) == 0) sred[d >> 5] = ss;
    __syncthreads();
    ss = sred[0] + sred[1] + sred[2] + sred[3];
    const float r = rsqrtf(ss * (1.0f / 128.0f) + 1e-6f);
    const float xn = x * r * w[d];
    xs[d] = xn;
    __syncthreads();
    const float rot = (d < 64) ? -xs[d + 64] : xs[d - 64];
    const size_t pidx = ((size_t)b * KVL + (size_t)(pos_off + t)) * HD + d;
    out[(((size_t)(b * heads + h)) * seq + t) * HD + d] = xn * cosb[pidx] + rot * sinb[pidx];
}

// ---------------- flash attention: one block per (b,h) ----------------
#define APAD 132
__global__ void __launch_bounds__(256)
attn_kernel(const float* __restrict__ Qm,
            const float* __restrict__ Km,
            const float* __restrict__ Vr,
            float* __restrict__ out)
{
    extern __shared__ float smf[];
    float* Qs = smf;
    float* Ks = smf + 128 * APAD;
    float* Vs = smf + 2 * 128 * APAD;

    const int b   = blockIdx.x >> 5;
    const int h   = blockIdx.x & 31;
    const int kvh = h >> 2;
    const int tid = threadIdx.x;
    const int ty = tid >> 4, tx = tid & 15;
    const int lrow = tid >> 1;
    const int lc0  = (tid & 1) * 64;

    const float scale = 0.08838834764831845f;

    const float* qg = Qm + ((size_t)(b * NH + h)) * QL * HD;
#pragma unroll
    for (int it = 0; it < 16; ++it) {
        const int col = lc0 + it * 4;
        float4 v = *(const float4*)(qg + lrow * HD + col);
        Qs[(col + 0) * APAD + lrow] = v.x * scale;
        Qs[(col + 1) * APAD + lrow] = v.y * scale;
        Qs[(col + 2) * APAD + lrow] = v.z * scale;
        Qs[(col + 3) * APAD + lrow] = v.w * scale;
    }

    float O[8][8];
    float mr[8], lr[8];
#pragma unroll
    for (int i = 0; i < 8; i++) {
        mr[i] = -1e30f; lr[i] = 0.f;
#pragma unroll
        for (int j = 0; j < 8; j++) O[i][j] = 0.f;
    }

    const float* kg = Km + ((size_t)(b * NKV + kvh)) * KVL * HD;
    const float* vg = Vr + (size_t)b * KVL * (NKV * HD) + kvh * HD;

    for (int c = 0; c < KVL / 128; ++c) {
        const int t0 = c * 128;
        __syncthreads();

#pragma unroll
        for (int it = 0; it < 16; ++it) {
            const int col = lc0 + it * 4;
            float4 v = *(const float4*)(kg + (size_t)(t0 + lrow) * HD + col);
            Ks[(col + 0) * APAD + lrow] = v.x;
            Ks[(col + 1) * APAD + lrow] = v.y;
            Ks[(col + 2) * APAD + lrow] = v.z;
            Ks[(col + 3) * APAD + lrow] = v.w;
        }
#pragma unroll
        for (int it = 0; it < 16; ++it) {
            const int idx = tid + it * 256;
            const int j = idx >> 5;
            const int c4 = (idx & 31) * 4;
            *(float4*)&Vs[j * APAD + c4] =
                *(const float4*)(vg + (size_t)(t0 + j) * (NKV * HD) + c4);
        }
        __syncthreads();

        float S[8][8];
#pragma unroll
        for (int i = 0; i < 8; i++)
#pragma unroll
            for (int j = 0; j < 8; j++) S[i][j] = 0.f;

#pragma unroll 2
        for (int d = 0; d < 128; ++d) {
            float a[8], bb[8];
            *(float4*)&a[0]  = *(const float4*)&Qs[d * APAD + ty * 8];
            *(float4*)&a[4]  = *(const float4*)&Qs[d * APAD + ty * 8 + 4];
            *(float4*)&bb[0] = *(const float4*)&Ks[d * APAD + tx * 8];
            *(float4*)&bb[4] = *(const float4*)&Ks[d * APAD + tx * 8 + 4];
#pragma unroll
            for (int i = 0; i < 8; i++)
#pragma unroll
                for (int j = 0; j < 8; j++)
                    S[i][j] += a[i] * bb[j];
        }

#pragma unroll
        for (int i = 0; i < 8; ++i) {
            float mx = S[i][0];
#pragma unroll
            for (int j = 1; j < 8; j++) mx = fmaxf(mx, S[i][j]);
#pragma unroll
            for (int off = 8; off > 0; off >>= 1)
                mx = fmaxf(mx, __shfl_xor_sync(0xffffffffu, mx, off));
            const float mn = fmaxf(mr[i], mx);
            const float corr = __expf(mr[i] - mn);
            float rs = 0.f;
#pragma unroll
            for (int j = 0; j < 8; j++) {
                const float p = __expf(S[i][j] - mn);
                S[i][j] = p;
                rs += p;
            }
#pragma unroll
            for (int off = 8; off > 0; off >>= 1)
                rs += __shfl_xor_sync(0xffffffffu, rs, off);
            lr[i] = lr[i] * corr + rs;
            mr[i] = mn;
#pragma unroll
            for (int j = 0; j < 8; j++) O[i][j] *= corr;
        }

        __syncthreads();
#pragma unroll
        for (int i = 0; i < 8; i++) {
            *(float4*)&Ks[(ty * 8 + i) * APAD + tx * 8] =
                make_float4(S[i][0], S[i][1], S[i][2], S[i][3]);
            *(float4*)&Ks[(ty * 8 + i) * APAD + tx * 8 + 4] =
                make_float4(S[i][4], S[i][5], S[i][6], S[i][7]);
        }
        __syncthreads();

#pragma unroll 4
        for (int j = 0; j < 128; ++j) {
            float bb[8];
            *(float4*)&bb[0] = *(const float4*)&Vs[j * APAD + tx * 8];
            *(float4*)&bb[4] = *(const float4*)&Vs[j * APAD + tx * 8 + 4];
#pragma unroll
            for (int i = 0; i < 8; i++) {
                const float p = Ks[(ty * 8 + i) * APAD + j];
#pragma unroll
                for (int jj = 0; jj < 8; jj++) O[i][jj] += p * bb[jj];
            }
        }
    }

#pragma unroll
    for (int i = 0; i < 8; i++) {
        const float inv = 1.0f / lr[i];
        const int q = ty * 8 + i;
        float* op = out + ((size_t)(b * QL + q)) * HIDN + h * HD + tx * 8;
        *(float4*)op       = make_float4(O[i][0] * inv, O[i][1] * inv, O[i][2] * inv, O[i][3] * inv);
        *(float4*)(op + 4) = make_float4(O[i][4] * inv, O[i][5] * inv, O[i][6] * inv, O[i][7] * inv);
    }
}

// ---------------- launcher ----------------
extern "C" void kernel_launch(void* const* d_in, const int* in_sizes, int n_in,
                              void* d_out, int out_size)
{
    const float* hidden = (const float*)d_in[0];
    const float* target = (const float*)d_in[1];
    const float* cosb   = (const float*)d_in[2];
    const float* sinb   = (const float*)d_in[3];
    const float* Wq     = (const float*)d_in[4];
    const float* Wk     = (const float*)d_in[5];
    const float* Wv     = (const float*)d_in[6];
    const float* Wo     = (const float*)d_in[7];
    const float* qw     = (const float*)d_in[8];
    const float* kw     = (const float*)d_in[9];
    float* out = (float*)d_out;

    float *q_raw, *Qp, *k_raw, *Kp, *v_raw, *attn;
    cudaGetSymbolAddress((void**)&q_raw, g_q_raw);
    cudaGetSymbolAddress((void**)&Qp,    g_Q);
    cudaGetSymbolAddress((void**)&k_raw, g_k_raw);
    cudaGetSymbolAddress((void**)&Kp,    g_K);
    cudaGetSymbolAddress((void**)&v_raw, g_v_raw);
    cudaGetSymbolAddress((void**)&attn,  g_attn);

    cudaFuncSetAttribute(gemm_mma<0>, cudaFuncAttributeMaxDynamicSharedMemorySize, GEMM_SMEM);
    cudaFuncSetAttribute(gemm_mma<1>, cudaFuncAttributeMaxDynamicSharedMemorySize, GEMM_SMEM);
    const int attn_smem = 3 * 128 * APAD * 4;
    cudaFuncSetAttribute(attn_kernel, cudaFuncAttributeMaxDynamicSharedMemorySize, attn_smem);

    // Q projection: [512,4096]
    gemm_mma<0><<<dim3(HIDN / 128, (4 * QL) / 128), 256, GEMM_SMEM>>>(
        hidden, nullptr, Wq, q_raw, 4 * QL, HIDN, HIDN);

    // K / V projections over concat(target, hidden): [33280,1024]
    gemm_mma<1><<<dim3((NKV * HD) / 128, (4 * KVL) / 128), 256, GEMM_SMEM>>>(
        hidden, target, Wk, k_raw, 4 * KVL, NKV * HD, HIDN);
    gemm_mma<1><<<dim3((NKV * HD) / 128, (4 * KVL) / 128), 256, GEMM_SMEM>>>(
        hidden, target, Wv, v_raw, 4 * KVL, NKV * HD, HIDN);

    // RMSNorm + RoPE
    norm_rope_kernel<<<4 * NH * QL, 128>>>(q_raw, Qp, qw, cosb, sinb, NH, QL, HIDN, CTXL);
    norm_rope_kernel<<<4 * NKV * KVL, 128>>>(k_raw, Kp, kw, cosb, sinb, NKV, KVL, NKV * HD, 0);

    // attention (fp32)
    attn_kernel<<<4 * NH, 256, attn_smem>>>(Qp, Kp, v_raw, attn);

    // output projection -> d_out
    gemm_mma<0><<<dim3(HIDN / 128, (4 * QL) / 128), 256, GEMM_SMEM>>>(
        attn, nullptr, Wo, out, 4 * QL, HIDN, HIDN);
}

// round 4
// speedup vs baseline: 2.6399x; 1.4064x over previous
#include <cuda_runtime.h>
#include <cuda_bf16.h>
#include <cstdint>

typedef __nv_bfloat16 bf16;

#define CTXL 8192
#define QL   128
#define KVL  8320
#define HIDN 4096
#define NH   32
#define NKV  8
#define HD   128
#define KVROWS (4 * KVL)          // 33280

// ---------------- scratch ----------------
__device__ float g_q_raw[4 * QL * HIDN];
__device__ float g_k_raw[(size_t)KVROWS * NKV * HD];

__device__ bf16 g_Wqh[(size_t)NH * HD * HIDN],  g_Wql[(size_t)NH * HD * HIDN];
__device__ bf16 g_Wkh[(size_t)NKV * HD * HIDN], g_Wkl[(size_t)NKV * HD * HIDN];
__device__ bf16 g_Wvh[(size_t)NKV * HD * HIDN], g_Wvl[(size_t)NKV * HD * HIDN];
__device__ bf16 g_Woh[(size_t)HIDN * NH * HD],  g_Wol[(size_t)HIDN * NH * HD];
__device__ bf16 g_hh[4 * QL * HIDN], g_hl[4 * QL * HIDN];
__device__ bf16 g_kvh[(size_t)KVROWS * HIDN], g_kvl[(size_t)KVROWS * HIDN];
__device__ bf16 g_Qh[4 * NH * QL * HD], g_Ql[4 * NH * QL * HD];
__device__ bf16 g_Kh[(size_t)4 * NKV * KVL * HD], g_Kl[(size_t)4 * NKV * KVL * HD];
__device__ bf16 g_Vh[(size_t)KVROWS * NKV * HD], g_Vl[(size_t)KVROWS * NKV * HD];
__device__ bf16 g_ah[4 * QL * HIDN], g_al[4 * QL * HIDN];

// ================= helpers =================
__device__ __forceinline__ uint32_t smem_u32(const void* p) {
    uint32_t a;
    asm("{ .reg .u64 t; cvta.to.shared.u64 t, %1; cvt.u32.u64 %0, t; }" : "=r"(a) : "l"(p));
    return a;
}
__device__ __forceinline__ void ldsm_x4(uint32_t addr, uint32_t* r) {
    asm volatile("ldmatrix.sync.aligned.m8n8.x4.shared.b16 {%0,%1,%2,%3}, [%4];"
                 : "=r"(r[0]), "=r"(r[1]), "=r"(r[2]), "=r"(r[3]) : "r"(addr));
}
__device__ __forceinline__ void ldsm_x4_t(uint32_t addr, uint32_t* r) {
    asm volatile("ldmatrix.sync.aligned.m8n8.x4.trans.shared.b16 {%0,%1,%2,%3}, [%4];"
                 : "=r"(r[0]), "=r"(r[1]), "=r"(r[2]), "=r"(r[3]) : "r"(addr));
}
__device__ __forceinline__ void mma16816(float* c, const uint32_t* a, const uint32_t* b) {
    asm volatile(
        "mma.sync.aligned.m16n8k16.row.col.f32.bf16.bf16.f32 "
        "{%0,%1,%2,%3}, {%4,%5,%6,%7}, {%8,%9}, {%0,%1,%2,%3};"
        : "+f"(c[0]), "+f"(c[1]), "+f"(c[2]), "+f"(c[3])
        : "r"(a[0]), "r"(a[1]), "r"(a[2]), "r"(a[3]), "r"(b[0]), "r"(b[1]));
}
__device__ __forceinline__ void cpa16(uint32_t dst, const void* src) {
    asm volatile("cp.async.cg.shared.global [%0], [%1], 16;" :: "r"(dst), "l"(src));
}
__device__ __forceinline__ void cpa_commit() { asm volatile("cp.async.commit_group;"); }
template <int N>
__device__ __forceinline__ void cpa_wait() { asm volatile("cp.async.wait_group %0;" :: "n"(N)); }

__device__ __forceinline__ void split1(float x, unsigned& h, unsigned& l) {
    bf16 hb = __float2bfloat16(x);
    float r = x - __bfloat162float(hb);
    bf16 lb = __float2bfloat16(r);
    h = (unsigned)__bfloat16_as_ushort(hb);
    l = (unsigned)__bfloat16_as_ushort(lb);
}

// ---------------- split kernels ----------------
__global__ void split_pair(const float* __restrict__ in, bf16* __restrict__ hi,
                           bf16* __restrict__ lo, size_t n8)
{
    const size_t i = (size_t)blockIdx.x * 256 + threadIdx.x;
    if (i >= n8) return;
    const float* s = in + i * 8;
    unsigned h[8], l[8];
#pragma unroll
    for (int k = 0; k < 8; k++) split1(s[k], h[k], l[k]);
    *(uint4*)(hi + i * 8) = make_uint4(h[0] | (h[1] << 16), h[2] | (h[3] << 16),
                                       h[4] | (h[5] << 16), h[6] | (h[7] << 16));
    *(uint4*)(lo + i * 8) = make_uint4(l[0] | (l[1] << 16), l[2] | (l[3] << 16),
                                       l[4] | (l[5] << 16), l[6] | (l[7] << 16));
}

__global__ void split_kv(const float* __restrict__ hidden, const float* __restrict__ target,
                         bf16* __restrict__ hi, bf16* __restrict__ lo)
{
    const int row = blockIdx.y;
    const int b = row / KVL;
    const int t = row - b * KVL;
    const float* src = (t < CTXL) ? target + ((size_t)b * CTXL + t) * HIDN
                                  : hidden + ((size_t)b * QL + (t - CTXL)) * HIDN;
    const int col = (blockIdx.x * 256 + threadIdx.x) * 8;
    const float* s = src + col;
    unsigned h[8], l[8];
#pragma unroll
    for (int k = 0; k < 8; k++) split1(s[k], h[k], l[k]);
    bf16* hp = hi + (size_t)row * HIDN + col;
    bf16* lp = lo + (size_t)row * HIDN + col;
    *(uint4*)hp = make_uint4(h[0] | (h[1] << 16), h[2] | (h[3] << 16),
                             h[4] | (h[5] << 16), h[6] | (h[7] << 16));
    *(uint4*)lp = make_uint4(l[0] | (l[1] << 16), l[2] | (l[3] << 16),
                             l[4] | (l[5] << 16), l[6] | (l[7] << 16));
}

// ============ GEMM v2: C[M,N] = A @ W^T, pre-split bf16 inputs, 3-term HMMA ============
#define ROWB 80
#define TILEB (128 * ROWB)
#define STAGEB (4 * TILEB)
#define GEMM_SMEM (2 * STAGEB)

template <int SPLITOUT>
__global__ void __launch_bounds__(256)
gemm_bf16(const bf16* __restrict__ Ah, const bf16* __restrict__ Al,
          const bf16* __restrict__ Bh, const bf16* __restrict__ Bl,
          float* __restrict__ C, bf16* __restrict__ Ch, bf16* __restrict__ Cl,
          int M, int N, int K)
{
    extern __shared__ char sm[];
    const uint32_t smb = smem_u32(sm);
    const int tid = threadIdx.x;
    const int l = tid & 31;
    const int w = tid >> 5;

    const int m0 = blockIdx.y * 128;
    const int n0 = blockIdx.x * 128;

    const int lrow = tid >> 1;
    const int lseg = tid & 1;
    const bf16* ah = Ah + (size_t)(m0 + lrow) * K + lseg * 16;
    const bf16* al = Al + (size_t)(m0 + lrow) * K + lseg * 16;
    const bf16* bh = Bh + (size_t)(n0 + lrow) * K + lseg * 16;
    const bf16* bl = Bl + (size_t)(n0 + lrow) * K + lseg * 16;
    const uint32_t soff = (uint32_t)lrow * ROWB + (uint32_t)lseg * 32;

    const int wm = (w & 3) * 32;
    const int wn = (w >> 2) * 64;
    const uint32_t a_off = (uint32_t)(wm + (l & 15)) * ROWB + (uint32_t)(l >> 4) * 16;
    const uint32_t b_off = (uint32_t)(wn + (l & 7) + ((l >> 4) & 1) * 8) * ROWB
                         + (uint32_t)((l >> 3) & 1) * 16;

    float acc[2][8][4];
#pragma unroll
    for (int i = 0; i < 2; i++)
#pragma unroll
        for (int j = 0; j < 8; j++)
#pragma unroll
            for (int k = 0; k < 4; k++) acc[i][j][k] = 0.f;

    const int nk = K / 32;

    // issue chunk 0
    {
        const uint32_t s0 = smb + soff;
        cpa16(s0,             ah);  cpa16(s0 + 16,             ah + 8);
        cpa16(s0 + TILEB,     al);  cpa16(s0 + TILEB + 16,     al + 8);
        cpa16(s0 + 2 * TILEB, bh);  cpa16(s0 + 2 * TILEB + 16, bh + 8);
        cpa16(s0 + 3 * TILEB, bl);  cpa16(s0 + 3 * TILEB + 16, bl + 8);
        cpa_commit();
    }

    for (int c = 0; c < nk; ++c) {
        if (c + 1 < nk) {
            const uint32_t s0 = smb + ((c + 1) & 1) * STAGEB + soff;
            const int ko = (c + 1) * 32;
            cpa16(s0,             ah + ko);  cpa16(s0 + 16,             ah + ko + 8);
            cpa16(s0 + TILEB,     al + ko);  cpa16(s0 + TILEB + 16,     al + ko + 8);
            cpa16(s0 + 2 * TILEB, bh + ko);  cpa16(s0 + 2 * TILEB + 16, bh + ko + 8);
            cpa16(s0 + 3 * TILEB, bl + ko);  cpa16(s0 + 3 * TILEB + 16, bl + ko + 8);
            cpa_commit();
            cpa_wait<1>();
        } else {
            cpa_wait<0>();
        }
        __syncthreads();

        const uint32_t base = smb + (uint32_t)(c & 1) * STAGEB;
#pragma unroll
        for (int ks = 0; ks < 2; ++ks) {
            uint32_t afh[2][4], afl[2][4];
            const uint32_t ka = base + a_off + ks * 32;
            ldsm_x4(ka, afh[0]);
            ldsm_x4(ka + 16 * ROWB, afh[1]);
            ldsm_x4(ka + TILEB, afl[0]);
            ldsm_x4(ka + TILEB + 16 * ROWB, afl[1]);

            const uint32_t kb = base + 2 * TILEB + b_off + ks * 32;
#pragma unroll
            for (int ng = 0; ng < 4; ++ng) {
                uint32_t bfh[4], bfl[4];
                ldsm_x4(kb + ng * 16 * ROWB, bfh);
                ldsm_x4(kb + TILEB + ng * 16 * ROWB, bfl);
#pragma unroll
                for (int mf = 0; mf < 2; ++mf) {
                    mma16816(acc[mf][ng * 2 + 0], afh[mf], bfh + 0);
                    mma16816(acc[mf][ng * 2 + 1], afh[mf], bfh + 2);
                    mma16816(acc[mf][ng * 2 + 0], afh[mf], bfl + 0);
                    mma16816(acc[mf][ng * 2 + 1], afh[mf], bfl + 2);
                    mma16816(acc[mf][ng * 2 + 0], afl[mf], bfh + 0);
                    mma16816(acc[mf][ng * 2 + 1], afl[mf], bfh + 2);
                }
            }
        }
        __syncthreads();
    }

#pragma unroll
    for (int mf = 0; mf < 2; ++mf) {
        const int r0 = m0 + wm + mf * 16 + (l >> 2);
#pragma unroll
        for (int nf = 0; nf < 8; ++nf) {
            const int col = n0 + wn + nf * 8 + (l & 3) * 2;
            if (SPLITOUT) {
                unsigned h0, l0, h1, l1, h2, l2, h3, l3;
                split1(acc[mf][nf][0], h0, l0);
                split1(acc[mf][nf][1], h1, l1);
                split1(acc[mf][nf][2], h2, l2);
                split1(acc[mf][nf][3], h3, l3);
                *(uint32_t*)(Ch + (size_t)r0 * N + col)       = h0 | (h1 << 16);
                *(uint32_t*)(Cl + (size_t)r0 * N + col)       = l0 | (l1 << 16);
                *(uint32_t*)(Ch + (size_t)(r0 + 8) * N + col) = h2 | (h3 << 16);
                *(uint32_t*)(Cl + (size_t)(r0 + 8) * N + col) = l2 | (l3 << 16);
            } else {
                float* p = C + (size_t)r0 * N + col;
                *(float2*)p                   = make_float2(acc[mf][nf][0], acc[mf][nf][1]);
                *(float2*)(p + 8 * (size_t)N) = make_float2(acc[mf][nf][2], acc[mf][nf][3]);
            }
        }
    }
}

// ---------------- fused RMSNorm + RoPE -> split bf16 planes ----------------
__global__ void norm_rope2(const float* __restrict__ raw, bf16* __restrict__ oh,
                           bf16* __restrict__ ol, const float* __restrict__ w,
                           const float* __restrict__ cosb, const float* __restrict__ sinb,
                           int heads, int seq, int rawld, int pos_off, float outscale)
{
    const int bid = blockIdx.x;
    const int t = bid % seq;
    const int h = (bid / seq) % heads;
    const int b = bid / (seq * heads);
    const int d = threadIdx.x;

    const float* rp = raw + ((size_t)(b * seq + t)) * rawld + h * HD;
    float x = rp[d];
    float ss = x * x;
#pragma unroll
    for (int off = 16; off > 0; off >>= 1)
        ss += __shfl_xor_sync(0xffffffffu, ss, off);

    __shared__ float sred[4];
    __shared__ float xs[128];
    if ((d & 31) == 0) sred[d >> 5] = ss;
    __syncthreads();
    ss = sred[0] + sred[1] + sred[2] + sred[3];
    const float r = rsqrtf(ss * (1.0f / 128.0f) + 1e-6f);
    const float xn = x * r * w[d];
    xs[d] = xn;
    __syncthreads();
    const float rot = (d < 64) ? -xs[d + 64] : xs[d - 64];
    const size_t pidx = ((size_t)b * KVL + (size_t)(pos_off + t)) * HD + d;
    const float y = (xn * cosb[pidx] + rot * sinb[pidx]) * outscale;
    unsigned hh, ll;
    split1(y, hh, ll);
    const size_t o = (((size_t)(b * heads + h)) * seq + t) * HD + d;
    oh[o] = __ushort_as_bfloat16((unsigned short)hh);
    ol[o] = __ushort_as_bfloat16((unsigned short)ll);
}

// ---------------- tensorized flash attention ----------------
#define QROWB 272
#define ATILE (128 * QROWB)         // 34816
#define ATT_SMEM (6 * ATILE)        // 208896

__global__ void __launch_bounds__(256)
attn2(const bf16* __restrict__ Qh, const bf16* __restrict__ Ql,
      const bf16* __restrict__ Kh, const bf16* __restrict__ Kl,
      const bf16* __restrict__ Vh, const bf16* __restrict__ Vl,
      bf16* __restrict__ Oh, bf16* __restrict__ Ol)
{
    extern __shared__ char sm[];
    const uint32_t smb = smem_u32(sm);
    const uint32_t sQh = smb, sQl = smb + ATILE, sKh = smb + 2 * ATILE,
                   sKl = smb + 3 * ATILE, sVh = smb + 4 * ATILE, sVl = smb + 5 * ATILE;

    const int b   = blockIdx.x >> 5;
    const int h   = blockIdx.x & 31;
    const int kvh = h >> 2;
    const int tid = threadIdx.x;
    const int l = tid & 31;
    const int w = tid >> 5;

    const int row = tid >> 1;          // 0..127
    const int half = tid & 1;          // 0/1 -> 64 elems
    const uint32_t ld_off = (uint32_t)row * QROWB + (uint32_t)half * 128;

    // Q load (once)
    {
        const bf16* qh = Qh + ((size_t)(b * NH + h) * QL + row) * HD + half * 64;
        const bf16* ql = Ql + ((size_t)(b * NH + h) * QL + row) * HD + half * 64;
#pragma unroll
        for (int i = 0; i < 8; i++) {
            cpa16(sQh + ld_off + i * 16, qh + i * 8);
            cpa16(sQl + ld_off + i * 16, ql + i * 8);
        }
        cpa_commit();
    }

    const bf16* kgh = Kh + (size_t)(b * NKV + kvh) * KVL * HD;
    const bf16* kgl = Kl + (size_t)(b * NKV + kvh) * KVL * HD;
    const bf16* vgh = Vh + (size_t)b * KVL * (NKV * HD) + kvh * HD;
    const bf16* vgl = Vl + (size_t)b * KVL * (NKV * HD) + kvh * HD;

    // fragment addressing
    const int wq = w * 16;   // warp q offset
    const uint32_t qa_off = (uint32_t)(wq + (l & 15)) * QROWB + (uint32_t)(l >> 4) * 16;
    const uint32_t kb_off = (uint32_t)((l & 7) + ((l >> 4) & 1) * 8) * QROWB
                          + (uint32_t)((l >> 3) & 1) * 16;
    const uint32_t vb_off = (uint32_t)(l & 15) * QROWB + (uint32_t)((l >> 4) & 1) * 16;

    float O[16][4];
    float mr[2], lr[2];
#pragma unroll
    for (int i = 0; i < 16; i++)
#pragma unroll
        for (int j = 0; j < 4; j++) O[i][j] = 0.f;
    mr[0] = mr[1] = -1e30f;
    lr[0] = lr[1] = 0.f;

    for (int c = 0; c < KVL / 128; ++c) {
        const int t0 = c * 128;
        __syncthreads();   // previous chunk fully consumed
        // K,V chunk loads
        {
            const bf16* s1 = kgh + (size_t)(t0 + row) * HD + half * 64;
            const bf16* s2 = kgl + (size_t)(t0 + row) * HD + half * 64;
            const bf16* s3 = vgh + (size_t)(t0 + row) * (NKV * HD) + half * 64;
            const bf16* s4 = vgl + (size_t)(t0 + row) * (NKV * HD) + half * 64;
#pragma unroll
            for (int i = 0; i < 8; i++) {
                cpa16(sKh + ld_off + i * 16, s1 + i * 8);
                cpa16(sKl + ld_off + i * 16, s2 + i * 8);
                cpa16(sVh + ld_off + i * 16, s3 + i * 8);
                cpa16(sVl + ld_off + i * 16, s4 + i * 8);
            }
            cpa_commit();
        }
        cpa_wait<0>();
        __syncthreads();

        // ---- S = Q K^T (3-term split) ----
        float S[16][4];
#pragma unroll
        for (int i = 0; i < 16; i++)
#pragma unroll
            for (int j = 0; j < 4; j++) S[i][j] = 0.f;

#pragma unroll
        for (int ds = 0; ds < 8; ++ds) {
            uint32_t aqh[4], aql[4];
            ldsm_x4(sQh + qa_off + ds * 32, aqh);
            ldsm_x4(sQl + qa_off + ds * 32, aql);
#pragma unroll
            for (int ng = 0; ng < 8; ++ng) {
                uint32_t bkh[4], bkl[4];
                ldsm_x4(sKh + kb_off + ng * 16 * QROWB + ds * 32, bkh);
                ldsm_x4(sKl + kb_off + ng * 16 * QROWB + ds * 32, bkl);
                mma16816(S[ng * 2 + 0], aqh, bkh + 0);
                mma16816(S[ng * 2 + 1], aqh, bkh + 2);
                mma16816(S[ng * 2 + 0], aqh, bkl + 0);
                mma16816(S[ng * 2 + 1], aqh, bkl + 2);
                mma16816(S[ng * 2 + 0], aql, bkh + 0);
                mma16816(S[ng * 2 + 1], aql, bkh + 2);
            }
        }

        // ---- online softmax on fragments (rows r=l>>2 and r+8) ----
#pragma unroll
        for (int rr = 0; rr < 2; ++rr) {
            float mx = -1e30f;
#pragma unroll
            for (int t = 0; t < 16; t++)
                mx = fmaxf(mx, fmaxf(S[t][rr * 2], S[t][rr * 2 + 1]));
            mx = fmaxf(mx, __shfl_xor_sync(0xffffffffu, mx, 1));
            mx = fmaxf(mx, __shfl_xor_sync(0xffffffffu, mx, 2));
            const float mn = fmaxf(mr[rr], mx);
            const float corr = __expf(mr[rr] - mn);
            float rs = 0.f;
#pragma unroll
            for (int t = 0; t < 16; t++) {
                float p0 = __expf(S[t][rr * 2] - mn);
                float p1 = __expf(S[t][rr * 2 + 1] - mn);
                S[t][rr * 2] = p0;
                S[t][rr * 2 + 1] = p1;
                rs += p0 + p1;
            }
            rs += __shfl_xor_sync(0xffffffffu, rs, 1);
            rs += __shfl_xor_sync(0xffffffffu, rs, 2);
            lr[rr] = lr[rr] * corr + rs;
            mr[rr] = mn;
#pragma unroll
            for (int t = 0; t < 16; t++) {
                O[t][rr * 2] *= corr;
                O[t][rr * 2 + 1] *= corr;
            }
        }

        // ---- O += P V (Ph*Vh + Ph*Vl + Pl*Vh) ----
#pragma unroll
        for (int s = 0; s < 8; ++s) {
            // repack P fragments from S tiles 2s, 2s+1
            uint32_t ph[4], pl[4];
#pragma unroll
            for (int q4 = 0; q4 < 4; ++q4) {
                const int t = 2 * s + (q4 >> 1);
                const float e0 = S[t][(q4 & 1) * 2];
                const float e1 = S[t][(q4 & 1) * 2 + 1];
                unsigned h0, l0, h1, l1;
                split1(e0, h0, l0);
                split1(e1, h1, l1);
                ph[q4] = h0 | (h1 << 16);
                pl[q4] = l0 | (l1 << 16);
            }
            // note a-frag order: a0,a1 = rows r,r+8 k0-7 (tile 2s regs 01 / 23); a2,a3 = k8-15 (tile 2s+1)
            uint32_t pfh[4] = {ph[0], ph[1], ph[2], ph[3]};
            uint32_t pfl[4] = {pl[0], pl[1], pl[2], pl[3]};
#pragma unroll
            for (int ng = 0; ng < 8; ++ng) {
                uint32_t vbh[4], vbl[4];
                ldsm_x4_t(sVh + vb_off + s * 16 * QROWB + ng * 32, vbh);
                ldsm_x4_t(sVl + vb_off + s * 16 * QROWB + ng * 32, vbl);
                mma16816(O[ng * 2 + 0], pfh, vbh + 0);
                mma16816(O[ng * 2 + 1], pfh, vbh + 2);
                mma16816(O[ng * 2 + 0], pfh, vbl + 0);
                mma16816(O[ng * 2 + 1], pfh, vbl + 2);
                mma16816(O[ng * 2 + 0], pfl, vbh + 0);
                mma16816(O[ng * 2 + 1], pfl, vbh + 2);
            }
        }
    }

    // ---- epilogue: normalize, split, store ----
    const float inv0 = 1.0f / lr[0];
    const float inv1 = 1.0f / lr[1];
    const int q0 = wq + (l >> 2);
#pragma unroll
    for (int nf = 0; nf < 16; ++nf) {
        const int col = nf * 8 + (l & 3) * 2;
        unsigned h0, l0, h1, l1;
        split1(O[nf][0] * inv0, h0, l0);
        split1(O[nf][1] * inv0, h1, l1);
        size_t o = ((size_t)(b * QL + q0)) * HIDN + h * HD + col;
        *(uint32_t*)(Oh + o) = h0 | (h1 << 16);
        *(uint32_t*)(Ol + o) = l0 | (l1 << 16);
        split1(O[nf][2] * inv1, h0, l0);
        split1(O[nf][3] * inv1, h1, l1);
        o = ((size_t)(b * QL + q0 + 8)) * HIDN + h * HD + col;
        *(uint32_t*)(Oh + o) = h0 | (h1 << 16);
        *(uint32_t*)(Ol + o) = l0 | (l1 << 16);
    }
}

// ---------------- launcher ----------------
extern "C" void kernel_launch(void* const* d_in, const int* in_sizes, int n_in,
                              void* d_out, int out_size)
{
    const float* hidden = (const float*)d_in[0];
    const float* target = (const float*)d_in[1];
    const float* cosb   = (const float*)d_in[2];
    const float* sinb   = (const float*)d_in[3];
    const float* Wq     = (const float*)d_in[4];
    const float* Wk     = (const float*)d_in[5];
    const float* Wv     = (const float*)d_in[6];
    const float* Wo     = (const float*)d_in[7];
    const float* qw     = (const float*)d_in[8];
    const float* kw     = (const float*)d_in[9];
    float* out = (float*)d_out;

    float *q_raw, *k_raw;
    bf16 *Wqh, *Wql, *Wkh, *Wkl, *Wvh, *Wvl, *Woh, *Wol;
    bf16 *hh, *hl, *kvh_, *kvl_, *Qhp, *Qlp, *Khp, *Klp, *Vhp, *Vlp, *ah, *al;
    cudaGetSymbolAddress((void**)&q_raw, g_q_raw);
    cudaGetSymbolAddress((void**)&k_raw, g_k_raw);
    cudaGetSymbolAddress((void**)&Wqh, g_Wqh); cudaGetSymbolAddress((void**)&Wql, g_Wql);
    cudaGetSymbolAddress((void**)&Wkh, g_Wkh); cudaGetSymbolAddress((void**)&Wkl, g_Wkl);
    cudaGetSymbolAddress((void**)&Wvh, g_Wvh); cudaGetSymbolAddress((void**)&Wvl, g_Wvl);
    cudaGetSymbolAddress((void**)&Woh, g_Woh); cudaGetSymbolAddress((void**)&Wol, g_Wol);
    cudaGetSymbolAddress((void**)&hh, g_hh);   cudaGetSymbolAddress((void**)&hl, g_hl);
    cudaGetSymbolAddress((void**)&kvh_, g_kvh); cudaGetSymbolAddress((void**)&kvl_, g_kvl);
    cudaGetSymbolAddress((void**)&Qhp, g_Qh);  cudaGetSymbolAddress((void**)&Qlp, g_Ql);
    cudaGetSymbolAddress((void**)&Khp, g_Kh);  cudaGetSymbolAddress((void**)&Klp, g_Kl);
    cudaGetSymbolAddress((void**)&Vhp, g_Vh);  cudaGetSymbolAddress((void**)&Vlp, g_Vl);
    cudaGetSymbolAddress((void**)&ah, g_ah);   cudaGetSymbolAddress((void**)&al, g_al);

    cudaFuncSetAttribute(gemm_bf16<0>, cudaFuncAttributeMaxDynamicSharedMemorySize, GEMM_SMEM);
    cudaFuncSetAttribute(gemm_bf16<1>, cudaFuncAttributeMaxDynamicSharedMemorySize, GEMM_SMEM);
    cudaFuncSetAttribute(attn2, cudaFuncAttributeMaxDynamicSharedMemorySize, ATT_SMEM);

    // ---- splits ----
    split_pair<<<(4 * QL * HIDN) / 2048, 256>>>(hidden, hh, hl, (size_t)(4 * QL * HIDN) / 8);
    split_pair<<<(NH * HD * HIDN) / 2048, 256>>>(Wq, Wqh, Wql, (size_t)(NH * HD * HIDN) / 8);
    split_pair<<<(NKV * HD * HIDN) / 2048, 256>>>(Wk, Wkh, Wkl, (size_t)(NKV * HD * HIDN) / 8);
    split_pair<<<(NKV * HD * HIDN) / 2048, 256>>>(Wv, Wvh, Wvl, (size_t)(NKV * HD * HIDN) / 8);
    split_pair<<<(HIDN * NH * HD) / 2048, 256>>>(Wo, Woh, Wol, (size_t)(HIDN * NH * HD) / 8);
    split_kv<<<dim3(HIDN / 2048, KVROWS), 256>>>(hidden, target, kvh_, kvl_);

    // ---- projections ----
    gemm_bf16<0><<<dim3(HIDN / 128, (4 * QL) / 128), 256, GEMM_SMEM>>>(
        hh, hl, Wqh, Wql, q_raw, nullptr, nullptr, 4 * QL, HIDN, HIDN);
    gemm_bf16<0><<<dim3((NKV * HD) / 128, KVROWS / 128), 256, GEMM_SMEM>>>(
        kvh_, kvl_, Wkh, Wkl, k_raw, nullptr, nullptr, KVROWS, NKV * HD, HIDN);
    gemm_bf16<1><<<dim3((NKV * HD) / 128, KVROWS / 128), 256, GEMM_SMEM>>>(
        kvh_, kvl_, Wvh, Wvl, nullptr, Vhp, Vlp, KVROWS, NKV * HD, HIDN);

    // ---- norm + rope (scale folded into Q) ----
    norm_rope2<<<4 * NH * QL, 128>>>(q_raw, Qhp, Qlp, qw, cosb, sinb, NH, QL, HIDN, CTXL,
                                     0.08838834764831845f);
    norm_rope2<<<4 * NKV * KVL, 128>>>(k_raw, Khp, Klp, kw, cosb, sinb, NKV, KVL, NKV * HD, 0,
                                       1.0f);

    // ---- attention ----
    attn2<<<4 * NH, 256, ATT_SMEM>>>(Qhp, Qlp, Khp, Klp, Vhp, Vlp, ah, al);

    // ---- output projection ----
    gemm_bf16<0><<<dim3(HIDN / 128, (4 * QL) / 128), 256, GEMM_SMEM>>>(
        ah, al, Woh, Wol, out, nullptr, nullptr, 4 * QL, HIDN, HIDN);
}